// round 13
// baseline (speedup 1.0000x reference)
#include <cuda_runtime.h>
#include <cstdint>

#define T_LEN   750
#define THREADS 192
#define RPC     8            // rows per CTA; grid = 4096/8 = 512 (single wave)
#define BUF_LEN 768
#define NSLOT   64
#define SLOT_STRIDE 32       // 128B stride

// exp(-x/2) = exp2(-x * 0.5*log2(e))
#define NEG_HALF_LOG2E (-0.7213475204444817f)

__device__ float        g_slots[NSLOT * SLOT_STRIDE];   // zero-init at load
__device__ unsigned int g_count;                        // zero-init at load

static __device__ __forceinline__ float ex2_approx(float x) {
    float r; asm("ex2.approx.ftz.f32 %0, %1;" : "=f"(r) : "f"(x)); return r;
}

static __device__ __forceinline__ void cp_async8(uint32_t saddr, const float* g) {
    asm volatile("cp.async.ca.shared.global [%0], [%1], 8;" :: "r"(saddr), "l"(g));
}

__global__ __launch_bounds__(THREADS, 6)
void ae_loss_kernel(const float* __restrict__ a0,
                    const float* __restrict__ a2,
                    float* __restrict__ out,
                    int NB) {
    __shared__ __align__(16) float buf[2][2][BUF_LEN];   // [stage][arr][t]
    __shared__ float rw[THREADS / 32];
    __shared__ float rn[THREADS / 32];
    __shared__ bool  is_last;

    const int b    = blockIdx.x;
    const int tid  = threadIdx.x;
    const int warp = tid >> 5, lane = tid & 31;

    const float* g0 = a0 + (size_t)b * RPC * T_LEN;
    const float* g2 = a2 + (size_t)b * RPC * T_LEN;

    uint32_t sb[2][2];
    sb[0][0] = (uint32_t)__cvta_generic_to_shared(&buf[0][0][0]);
    sb[0][1] = (uint32_t)__cvta_generic_to_shared(&buf[0][1][0]);
    sb[1][0] = (uint32_t)__cvta_generic_to_shared(&buf[1][0][0]);
    sb[1][1] = (uint32_t)__cvta_generic_to_shared(&buf[1][1][0]);

    // Prefetch row 0 into stage 0 (rows are 8B-aligned: 750 even)
    for (int q = tid; q < T_LEN / 2; q += THREADS) {
        cp_async8(sb[0][0] + q * 8, g0 + 2 * q);
        cp_async8(sb[0][1] + q * 8, g2 + 2 * q);
    }
    asm volatile("cp.async.commit_group;" ::: "memory");

    const int i_base = tid * 4;
    float acc2a = 0.0f, acc2b = 0.0f, acc1 = 0.0f;  // symmetric-pair accumulators
    float wextra = 0.0f;                            // boundary extras (tid<8)
    float snorm  = 0.0f;                            // thread 0: sum of sqrt(nsq_r)

#pragma unroll
    for (int r = 0; r < RPC; r++) {
        const int st = r & 1;
        if (r + 1 < RPC) {
            const int nst = (r + 1) & 1;
            const float* n0 = g0 + (size_t)(r + 1) * T_LEN;
            const float* n2 = g2 + (size_t)(r + 1) * T_LEN;
            for (int q = tid; q < T_LEN / 2; q += THREADS) {
                cp_async8(sb[nst][0] + q * 8, n0 + 2 * q);
                cp_async8(sb[nst][1] + q * 8, n2 + 2 * q);
            }
            asm volatile("cp.async.commit_group;" ::: "memory");
            asm volatile("cp.async.wait_group 1;" ::: "memory");  // row r ready
        } else {
            asm volatile("cp.async.wait_group 0;" ::: "memory");
        }
        __syncthreads();

        const float* s0 = buf[st][0];
        const float* s2 = buf[st][1];
        float nsq = 0.0f;

        if (i_base < T_LEN) {
            if (i_base + 9 <= T_LEN - 1) {
                // Fast path: 3x LDS.128 per array; uses v[0..9] only
                // (thread 185 reads smem[750..751] garbage into unused slots)
                float v0[12], v2[12];
                const float4* p0 = reinterpret_cast<const float4*>(s0 + i_base);
                const float4* p2 = reinterpret_cast<const float4*>(s2 + i_base);
#pragma unroll
                for (int q = 0; q < 3; q++) {
                    float4 t0 = p0[q], t2 = p2[q];
                    v0[4*q]=t0.x; v0[4*q+1]=t0.y; v0[4*q+2]=t0.z; v0[4*q+3]=t0.w;
                    v2[4*q]=t2.x; v2[4*q+1]=t2.y; v2[4*q+2]=t2.z; v2[4*q+3]=t2.w;
                }
#pragma unroll
                for (int c = 0; c < 4; c++) {
                    const float x0 = v0[c], x2 = v2[c];
                    const float d = x0 - x2;
                    nsq = fmaf(d, d, nsq);
#pragma unroll
                    for (int k = 1; k <= 6; k++) {
                        const float e = ex2_approx(fabsf(x0 - v0[c+k]) * NEG_HALF_LOG2E);
                        const float t = e * fabsf(x2 - v2[c+k]);
                        if      (k <= 2) acc2a += t;
                        else if (k <= 4) acc2b += t;
                        else             acc1  += t;
                    }
                }
            } else {
                // Tail threads (186,187): scalar smem reads, range-masked
#pragma unroll
                for (int c = 0; c < 4; c++) {
                    const int i = i_base + c;
                    if (i < T_LEN) {
                        const float x0 = s0[i], x2 = s2[i];
                        const float d = x0 - x2;
                        nsq = fmaf(d, d, nsq);
#pragma unroll
                        for (int k = 1; k <= 6; k++) {
                            if (i + k < T_LEN) {
                                const float e = ex2_approx(fabsf(x0 - s0[i+k]) * NEG_HALF_LOG2E);
                                const float t = e * fabsf(x2 - s2[i+k]);
                                if      (k <= 2) acc2a += t;
                                else if (k <= 4) acc2b += t;
                                else             acc1  += t;
                            }
                        }
                    }
                }
            }
        }

        // Clamped-boundary extras for this row (replicates reference padding):
        //   left : u=1..5     -> (6-u)   * term(u, 0)
        //   right: u=746..748 -> (u-745) * term(u, 749)
        if (tid < 8) {
            int u, p; float mult;
            if (tid < 5) { u = tid + 1;   p = 0;         mult = (float)(5 - tid); }
            else         { u = 741 + tid; p = T_LEN - 1; mult = (float)(tid - 4); }
            const float e = ex2_approx(fabsf(s0[u] - s0[p]) * NEG_HALF_LOG2E);
            wextra = fmaf(mult * e, fabsf(s2[u] - s2[p]), wextra);
        }

        // Per-row nsq block reduction (sqrt is per row)
#pragma unroll
        for (int o = 16; o > 0; o >>= 1)
            nsq += __shfl_down_sync(0xFFFFFFFFu, nsq, o);
        if (lane == 0) rn[warp] = nsq;
        __syncthreads();   // also orders: all reads of buf[st] done before reuse
        if (tid == 0) {
            float n = rn[0] + rn[1] + rn[2] + rn[3] + rn[4] + rn[5];
            snorm += sqrtf(n);
        }
        // (thread 0's rn read is safe: other threads cannot rewrite rn until
        //  they pass the next iteration's post-wait __syncthreads, which
        //  requires thread 0 to arrive there first.)
    }

    float wsum = fmaf(2.0f, acc2a + acc2b, acc1) + wextra;
#pragma unroll
    for (int o = 16; o > 0; o >>= 1)
        wsum += __shfl_down_sync(0xFFFFFFFFu, wsum, o);
    if (lane == 0) rw[warp] = wsum;
    __syncthreads();

    if (tid == 0) {
        float w = rw[0] + rw[1] + rw[2] + rw[3] + rw[4] + rw[5];
        atomicAdd(&g_slots[(b & (NSLOT - 1)) * SLOT_STRIDE], w + 0.1f * snorm);
        __threadfence();
        unsigned int prev = atomicAdd(&g_count, 1u);
        is_last = (prev == (unsigned int)(NB - 1));
    }
    __syncthreads();

    // Last block: reduce slots, write result, reset state for next replay.
    if (is_last) {
        float v = 0.0f;
        if (tid < NSLOT)
            v = atomicAdd(&g_slots[tid * SLOT_STRIDE], 0.0f);  // L2-coherent read
#pragma unroll
        for (int o = 16; o > 0; o >>= 1)
            v += __shfl_down_sync(0xFFFFFFFFu, v, o);
        if (lane == 0 && warp < 2) rw[warp] = v;
        __syncthreads();
        if (tid == 0) {
            out[0] = rw[0] + rw[1];
            g_count = 0u;
        }
        __syncthreads();
        if (tid < NSLOT) g_slots[tid * SLOT_STRIDE] = 0.0f;
    }
}

extern "C" void kernel_launch(void* const* d_in, const int* in_sizes, int n_in,
                              void* d_out, int out_size) {
    const float* a0 = (const float*)d_in[0];
    const float* a2 = (const float*)d_in[1];
    float* out = (float*)d_out;

    const int B  = in_sizes[0] / T_LEN;   // 4096
    const int NB = B / RPC;               // 512

    ae_loss_kernel<<<NB, THREADS>>>(a0, a2, out, NB);
}

// round 14
// speedup vs baseline: 1.0392x; 1.0392x over previous
#include <cuda_runtime.h>
#include <cstdint>

#define T_LEN   750
#define THREADS 192
#define RPC     8            // rows per CTA; grid = 4096/8 = 512
#define STAGES  4            // pipeline depth 3 (prefetch r+3 while computing r)
#define BUF_LEN 768
#define NSLOT   64
#define SLOT_STRIDE 32       // 128B stride

// exp(-x/2) = exp2(-x * 0.5*log2(e))
#define NEG_HALF_LOG2E (-0.7213475204444817f)

__device__ float        g_slots[NSLOT * SLOT_STRIDE];   // zero-init at load
__device__ unsigned int g_count;                        // zero-init at load

static __device__ __forceinline__ float ex2_approx(float x) {
    float r; asm("ex2.approx.ftz.f32 %0, %1;" : "=f"(r) : "f"(x)); return r;
}
static __device__ __forceinline__ void cp_async8(uint32_t saddr, const float* g) {
    asm volatile("cp.async.ca.shared.global [%0], [%1], 8;" :: "r"(saddr), "l"(g));
}

__global__ __launch_bounds__(THREADS, 4)
void ae_loss_kernel(const float* __restrict__ a0,
                    const float* __restrict__ a2,
                    float* __restrict__ out,
                    int NB) {
    __shared__ __align__(16) float buf[STAGES][2][BUF_LEN];
    __shared__ float rn_row[RPC];        // per-row nsq sums (atomic targets)
    __shared__ float rw[THREADS / 32];
    __shared__ bool  is_last;

    const int b    = blockIdx.x;
    const int tid  = threadIdx.x;
    const int warp = tid >> 5, lane = tid & 31;
    const bool last_block = (b == NB - 1);

    const float* g0 = a0 + (size_t)b * RPC * T_LEN;
    const float* g2 = a2 + (size_t)b * RPC * T_LEN;

    uint32_t sb0[STAGES], sb1[STAGES];
#pragma unroll
    for (int s = 0; s < STAGES; s++) {
        sb0[s] = (uint32_t)__cvta_generic_to_shared(&buf[s][0][0]);
        sb1[s] = (uint32_t)__cvta_generic_to_shared(&buf[s][1][0]);
    }

    if (tid < RPC) rn_row[tid] = 0.0f;

    // Prefetch one row into stage (r & 3). Each thread covers floats
    // [tid*4, tid*4+4) of the row via 2x cp.async.8 per array (8B-aligned:
    // row base offsets are multiples of 750*4B, 8 | 3000). Threads 188..191
    // stage floats 750..767 = head of the next row (never read by compute).
    // For the very last row of the whole tensor, tids >= 187 would read OOB:
    // scalar clamped fallback (visible to consumers via later barriers).
    auto prefetch = [&](int r) {
        const int st = r & (STAGES - 1);
        const float* n0 = g0 + (size_t)r * T_LEN;
        const float* n2 = g2 + (size_t)r * T_LEN;
        const int off = tid * 4;
        if (last_block && r == RPC - 1 && tid >= 187) {
#pragma unroll
            for (int m = 0; m < 4; m++) {
                int c = off + m; c = c > T_LEN - 1 ? T_LEN - 1 : c;
                buf[st][0][off + m] = n0[c];
                buf[st][1][off + m] = n2[c];
            }
        } else {
            cp_async8(sb0[st] + tid * 16,     n0 + off);
            cp_async8(sb0[st] + tid * 16 + 8, n0 + off + 2);
            cp_async8(sb1[st] + tid * 16,     n2 + off);
            cp_async8(sb1[st] + tid * 16 + 8, n2 + off + 2);
        }
        asm volatile("cp.async.commit_group;" ::: "memory");
    };

    prefetch(0); prefetch(1); prefetch(2);

    const int i_base = tid * 4;
    float acc2a = 0.0f, acc2b = 0.0f, acc1 = 0.0f;
    float wextra = 0.0f;

#pragma unroll
    for (int r = 0; r < RPC; r++) {
        // Row r's group complete when <= (groups issued - (r+1)) remain pending.
        if      (r < RPC - 2) asm volatile("cp.async.wait_group 2;" ::: "memory");
        else if (r == RPC - 2) asm volatile("cp.async.wait_group 1;" ::: "memory");
        else                   asm volatile("cp.async.wait_group 0;" ::: "memory");
        __syncthreads();   // visibility of row r + all warps done with row r-1's stage

        if (r + 3 < RPC) prefetch(r + 3);   // reuses stage (r-1)&3: safe post-barrier

        const int st = r & (STAGES - 1);
        const float* s0 = buf[st][0];
        const float* s2 = buf[st][1];
        float nsq = 0.0f;

        if (i_base < T_LEN) {
            if (i_base + 9 <= T_LEN - 1) {
                float v0[12], v2[12];
                const float4* p0 = reinterpret_cast<const float4*>(s0 + i_base);
                const float4* p2 = reinterpret_cast<const float4*>(s2 + i_base);
#pragma unroll
                for (int q = 0; q < 3; q++) {
                    float4 t0 = p0[q], t2 = p2[q];
                    v0[4*q]=t0.x; v0[4*q+1]=t0.y; v0[4*q+2]=t0.z; v0[4*q+3]=t0.w;
                    v2[4*q]=t2.x; v2[4*q+1]=t2.y; v2[4*q+2]=t2.z; v2[4*q+3]=t2.w;
                }
#pragma unroll
                for (int c = 0; c < 4; c++) {
                    const float x0 = v0[c], x2 = v2[c];
                    const float d = x0 - x2;
                    nsq = fmaf(d, d, nsq);
#pragma unroll
                    for (int k = 1; k <= 6; k++) {
                        const float e = ex2_approx(fabsf(x0 - v0[c+k]) * NEG_HALF_LOG2E);
                        const float t = e * fabsf(x2 - v2[c+k]);
                        if      (k <= 2) acc2a += t;
                        else if (k <= 4) acc2b += t;
                        else             acc1  += t;
                    }
                }
            } else {
                // Tail threads (186,187): scalar smem reads, range-masked
#pragma unroll
                for (int c = 0; c < 4; c++) {
                    const int i = i_base + c;
                    if (i < T_LEN) {
                        const float x0 = s0[i], x2 = s2[i];
                        const float d = x0 - x2;
                        nsq = fmaf(d, d, nsq);
#pragma unroll
                        for (int k = 1; k <= 6; k++) {
                            if (i + k < T_LEN) {
                                const float e = ex2_approx(fabsf(x0 - s0[i+k]) * NEG_HALF_LOG2E);
                                const float t = e * fabsf(x2 - s2[i+k]);
                                if      (k <= 2) acc2a += t;
                                else if (k <= 4) acc2b += t;
                                else             acc1  += t;
                            }
                        }
                    }
                }
            }
        }

        // Clamped-boundary extras (replicates reference padding; verified exact):
        //   left : u=1..5     -> (6-u)   * term(u, 0)
        //   right: u=746..748 -> (u-745) * term(u, 749)
        if (tid < 8) {
            int u, p; float mult;
            if (tid < 5) { u = tid + 1;   p = 0;         mult = (float)(5 - tid); }
            else         { u = 741 + tid; p = T_LEN - 1; mult = (float)(tid - 4); }
            const float e = ex2_approx(fabsf(s0[u] - s0[p]) * NEG_HALF_LOG2E);
            wextra = fmaf(mult * e, fabsf(s2[u] - s2[p]), wextra);
        }

        // Per-row nsq: warp shuffle-reduce + one smem atomic (no extra barrier)
#pragma unroll
        for (int o = 16; o > 0; o >>= 1)
            nsq += __shfl_down_sync(0xFFFFFFFFu, nsq, o);
        if (lane == 0) atomicAdd(&rn_row[r], nsq);
    }

    float wsum = fmaf(2.0f, acc2a + acc2b, acc1) + wextra;
#pragma unroll
    for (int o = 16; o > 0; o >>= 1)
        wsum += __shfl_down_sync(0xFFFFFFFFu, wsum, o);
    if (lane == 0) rw[warp] = wsum;
    __syncthreads();   // rn_row atomics + rw visible

    if (tid == 0) {
        float w = rw[0] + rw[1] + rw[2] + rw[3] + rw[4] + rw[5];
        float snorm = 0.0f;
#pragma unroll
        for (int q = 0; q < RPC; q++) snorm += sqrtf(rn_row[q]);
        atomicAdd(&g_slots[(b & (NSLOT - 1)) * SLOT_STRIDE], w + 0.1f * snorm);
        __threadfence();
        unsigned int prev = atomicAdd(&g_count, 1u);
        is_last = (prev == (unsigned int)(NB - 1));
    }
    __syncthreads();

    // Last block: reduce slots, write result, reset state for next replay.
    if (is_last) {
        float v = 0.0f;
        if (tid < NSLOT)
            v = atomicAdd(&g_slots[tid * SLOT_STRIDE], 0.0f);  // L2-coherent read
#pragma unroll
        for (int o = 16; o > 0; o >>= 1)
            v += __shfl_down_sync(0xFFFFFFFFu, v, o);
        if (lane == 0 && warp < 2) rw[warp] = v;
        __syncthreads();
        if (tid == 0) {
            out[0] = rw[0] + rw[1];
            g_count = 0u;
        }
        __syncthreads();
        if (tid < NSLOT) g_slots[tid * SLOT_STRIDE] = 0.0f;
    }
}

extern "C" void kernel_launch(void* const* d_in, const int* in_sizes, int n_in,
                              void* d_out, int out_size) {
    const float* a0 = (const float*)d_in[0];
    const float* a2 = (const float*)d_in[1];
    float* out = (float*)d_out;

    const int B  = in_sizes[0] / T_LEN;   // 4096
    const int NB = B / RPC;               // 512

    ae_loss_kernel<<<NB, THREADS>>>(a0, a2, out, NB);
}

// round 15
// speedup vs baseline: 1.1604x; 1.1167x over previous
#include <cuda_runtime.h>
#include <cstdint>

#define T_LEN   750
#define THREADS 192
#define RPC     4            // rows per CTA; grid = 4096/4 = 1024
#define NCHUNK  2            // 2 chunks of 2 rows; 2 rows = 6000 B (16B multiple)
#define CHUNK_BYTES 6000
#define NSLOT   64
#define SLOT_STRIDE 32       // 128B stride

// exp(-x/2) = exp2(-x * 0.5*log2(e))
#define NEG_HALF_LOG2E (-0.7213475204444817f)

__device__ float        g_slots[NSLOT * SLOT_STRIDE];   // zero-init at load
__device__ unsigned int g_count;                        // zero-init at load

static __device__ __forceinline__ float ex2_approx(float x) {
    float r; asm("ex2.approx.ftz.f32 %0, %1;" : "=f"(r) : "f"(x)); return r;
}

static __device__ __forceinline__ void mbar_init(uint32_t mbar, uint32_t cnt) {
    asm volatile("mbarrier.init.shared.b64 [%0], %1;" :: "r"(mbar), "r"(cnt) : "memory");
}
static __device__ __forceinline__ void mbar_expect_tx(uint32_t mbar, uint32_t bytes) {
    asm volatile("mbarrier.arrive.expect_tx.shared.b64 _, [%0], %1;"
                 :: "r"(mbar), "r"(bytes) : "memory");
}
static __device__ __forceinline__ void bulk_g2s(uint32_t dst, const void* src,
                                                uint32_t bytes, uint32_t mbar) {
    asm volatile("cp.async.bulk.shared::cta.global.mbarrier::complete_tx::bytes "
                 "[%0], [%1], %2, [%3];"
                 :: "r"(dst), "l"(src), "r"(bytes), "r"(mbar) : "memory");
}
static __device__ __forceinline__ void mbar_wait(uint32_t mbar, uint32_t parity) {
    uint32_t done;
    asm volatile("{\n\t.reg .pred p;\n\t"
                 "mbarrier.try_wait.parity.acquire.cta.shared::cta.b64 p, [%1], %2;\n\t"
                 "selp.b32 %0, 1, 0, p;\n\t}"
                 : "=r"(done) : "r"(mbar), "r"(parity) : "memory");
    if (!done) {
        asm volatile("{\n\t.reg .pred P1;\n\t"
                     "WL_%=:\n\t"
                     "mbarrier.try_wait.parity.acquire.cta.shared::cta.b64 P1, [%0], %1, 0x989680;\n\t"
                     "@P1 bra.uni WD_%=;\n\t"
                     "bra.uni WL_%=;\n\t"
                     "WD_%=:\n\t}"
                     :: "r"(mbar), "r"(parity) : "memory");
    }
}

__global__ __launch_bounds__(THREADS, 8)
void ae_loss_kernel(const float* __restrict__ a0,
                    const float* __restrict__ a2,
                    float* __restrict__ out,
                    int NB) {
    __shared__ __align__(16) float s0buf[RPC * T_LEN];   // 3000 floats
    __shared__ __align__(16) float s2buf[RPC * T_LEN];
    __shared__ __align__(8)  uint64_t mbar_store[NCHUNK];
    __shared__ float rn_row[RPC];
    __shared__ float rw[THREADS / 32];
    __shared__ bool  is_last;

    const int b    = blockIdx.x;
    const int tid  = threadIdx.x;
    const int warp = tid >> 5, lane = tid & 31;

    const char* g0 = (const char*)(a0) + (size_t)b * RPC * T_LEN * 4;
    const char* g2 = (const char*)(a2) + (size_t)b * RPC * T_LEN * 4;
    const uint32_t sm0 = (uint32_t)__cvta_generic_to_shared(s0buf);
    const uint32_t sm2 = (uint32_t)__cvta_generic_to_shared(s2buf);
    const uint32_t mb  = (uint32_t)__cvta_generic_to_shared(mbar_store);

    if (tid < RPC) rn_row[tid] = 0.0f;
    if (tid == 0) {
        mbar_init(mb,     1);
        mbar_init(mb + 8, 1);
        asm volatile("fence.proxy.async.shared::cta;" ::: "memory");
        // Issue ALL bulk loads up-front: TMA engine queues them, DRAM streams.
#pragma unroll
        for (int c = 0; c < NCHUNK; c++) {
            mbar_expect_tx(mb + c * 8, 2 * CHUNK_BYTES);
            bulk_g2s(sm0 + c * CHUNK_BYTES, g0 + c * CHUNK_BYTES, CHUNK_BYTES, mb + c * 8);
            bulk_g2s(sm2 + c * CHUNK_BYTES, g2 + c * CHUNK_BYTES, CHUNK_BYTES, mb + c * 8);
        }
    }
    __syncthreads();   // mbar visibility to all waiting threads

    const int i_base = tid * 4;
    float acc2a = 0.0f, acc2b = 0.0f, acc1 = 0.0f;
    float wextra = 0.0f;

#pragma unroll
    for (int r = 0; r < RPC; r++) {
        if ((r & 1) == 0) mbar_wait(mb + (r >> 1) * 8, 0);  // chunk (r/2) ready

        const float* s0 = s0buf + r * T_LEN;
        const float* s2 = s2buf + r * T_LEN;
        float nsq = 0.0f;

        if (i_base < T_LEN) {
            if (i_base + 9 <= T_LEN - 1) {
                // Fast path: 5x LDS.64 per array (row base offsets even -> aligned)
                float v0[10], v2[10];
                const float2* p0 = reinterpret_cast<const float2*>(s0 + i_base);
                const float2* p2 = reinterpret_cast<const float2*>(s2 + i_base);
#pragma unroll
                for (int q = 0; q < 5; q++) {
                    float2 t0 = p0[q], t2 = p2[q];
                    v0[2*q] = t0.x; v0[2*q+1] = t0.y;
                    v2[2*q] = t2.x; v2[2*q+1] = t2.y;
                }
#pragma unroll
                for (int c = 0; c < 4; c++) {
                    const float x0 = v0[c], x2 = v2[c];
                    const float d = x0 - x2;
                    nsq = fmaf(d, d, nsq);
#pragma unroll
                    for (int k = 1; k <= 6; k++) {
                        const float e = ex2_approx(fabsf(x0 - v0[c+k]) * NEG_HALF_LOG2E);
                        const float t = e * fabsf(x2 - v2[c+k]);
                        if      (k <= 2) acc2a += t;
                        else if (k <= 4) acc2b += t;
                        else             acc1  += t;
                    }
                }
            } else {
                // Tail threads (186,187): scalar smem reads, range-masked
#pragma unroll
                for (int c = 0; c < 4; c++) {
                    const int i = i_base + c;
                    if (i < T_LEN) {
                        const float x0 = s0[i], x2 = s2[i];
                        const float d = x0 - x2;
                        nsq = fmaf(d, d, nsq);
#pragma unroll
                        for (int k = 1; k <= 6; k++) {
                            if (i + k < T_LEN) {
                                const float e = ex2_approx(fabsf(x0 - s0[i+k]) * NEG_HALF_LOG2E);
                                const float t = e * fabsf(x2 - s2[i+k]);
                                if      (k <= 2) acc2a += t;
                                else if (k <= 4) acc2b += t;
                                else             acc1  += t;
                            }
                        }
                    }
                }
            }
        }

        // Clamped-boundary extras (replicates reference padding; verified exact):
        //   left : u=1..5     -> (6-u)   * term(u, 0)
        //   right: u=746..748 -> (u-745) * term(u, 749)
        if (tid < 8) {
            int u, p; float mult;
            if (tid < 5) { u = tid + 1;   p = 0;         mult = (float)(5 - tid); }
            else         { u = 741 + tid; p = T_LEN - 1; mult = (float)(tid - 4); }
            const float e = ex2_approx(fabsf(s0[u] - s0[p]) * NEG_HALF_LOG2E);
            wextra = fmaf(mult * e, fabsf(s2[u] - s2[p]), wextra);
        }

        // Per-row nsq: warp shuffle-reduce + one smem atomic (no barrier)
#pragma unroll
        for (int o = 16; o > 0; o >>= 1)
            nsq += __shfl_down_sync(0xFFFFFFFFu, nsq, o);
        if (lane == 0) atomicAdd(&rn_row[r], nsq);
    }

    float wsum = fmaf(2.0f, acc2a + acc2b, acc1) + wextra;
#pragma unroll
    for (int o = 16; o > 0; o >>= 1)
        wsum += __shfl_down_sync(0xFFFFFFFFu, wsum, o);
    if (lane == 0) rw[warp] = wsum;
    __syncthreads();   // rn_row atomics + rw visible to thread 0

    if (tid == 0) {
        float w = rw[0] + rw[1] + rw[2] + rw[3] + rw[4] + rw[5];
        float snorm = 0.0f;
#pragma unroll
        for (int q = 0; q < RPC; q++) snorm += sqrtf(rn_row[q]);
        atomicAdd(&g_slots[(b & (NSLOT - 1)) * SLOT_STRIDE], w + 0.1f * snorm);
        __threadfence();
        unsigned int prev = atomicAdd(&g_count, 1u);
        is_last = (prev == (unsigned int)(NB - 1));
    }
    __syncthreads();

    // Last block: reduce slots, write result, reset state for next replay.
    if (is_last) {
        float v = 0.0f;
        if (tid < NSLOT)
            v = atomicAdd(&g_slots[tid * SLOT_STRIDE], 0.0f);  // L2-coherent read
#pragma unroll
        for (int o = 16; o > 0; o >>= 1)
            v += __shfl_down_sync(0xFFFFFFFFu, v, o);
        if (lane == 0 && warp < 2) rw[warp] = v;
        __syncthreads();
        if (tid == 0) {
            out[0] = rw[0] + rw[1];
            g_count = 0u;
        }
        __syncthreads();
        if (tid < NSLOT) g_slots[tid * SLOT_STRIDE] = 0.0f;
    }
}

extern "C" void kernel_launch(void* const* d_in, const int* in_sizes, int n_in,
                              void* d_out, int out_size) {
    const float* a0 = (const float*)d_in[0];
    const float* a2 = (const float*)d_in[1];
    float* out = (float*)d_out;

    const int B  = in_sizes[0] / T_LEN;   // 4096
    const int NB = B / RPC;               // 1024

    ae_loss_kernel<<<NB, THREADS>>>(a0, a2, out, NB);
}